// round 3
// baseline (speedup 1.0000x reference)
#include <cuda_runtime.h>

#define Bb 8
#define Tt 2048
#define Cc 4096
#define Uu 200
#define Kk 8                       // u-values per lane
#define NLANE 25                   // 25 * 8 = 200
#define NEGF (-1e30f)
#define LOG2E 1.4426950408889634f
#define LN2   0.6931471805599453f

// Minimax (Chebyshev, deg 4) coefficients for log2(1+e), e in [0,1].
// abs err ~8.5e-5; derived from ln(3+u) Chebyshev expansion, scaled by log2e.
#define Q0 0.00010995f
#define Q1 1.4372102f
#define Q2 (-0.6726796f)
#define Q3 0.3152093f
#define Q4 (-0.0799299f)

// Scratch (no cudaMalloc allowed): lpt2 [B,T,U] fp32 (log2-scaled) = 13.1 MB.
__device__ float g_lpt[Bb * Tt * Uu];
__device__ float g_final[Bb];
__device__ int   g_is64;

__device__ __forceinline__ float ex2f(float x) {
    float r; asm("ex2.approx.f32 %0, %1;" : "=f"(r) : "f"(x)); return r;
}

// ---------------------------------------------------------------------------
// Kernel 0: detect int64 vs int32 targets (odd 32-bit words all zero => int64).
// ---------------------------------------------------------------------------
__global__ void detect_kernel(const int* __restrict__ t32) {
    int all0 = 1;
    #pragma unroll
    for (int i = 1; i < 64; i += 2) all0 &= (t32[i] == 0);
    g_is64 = all0;
}

// ---------------------------------------------------------------------------
// Kernel 1: per row r=b*T+t: lse = logsumexp(inputs[r,:]);
// g_lpt[r*U+u] = (inputs[r,targets[b,u]] - lse) * LOG2E   (log2 domain)
// ---------------------------------------------------------------------------
__global__ __launch_bounds__(256) void lpt_kernel(const float* __restrict__ inp,
                                                  const int* __restrict__ t32) {
    const int r = blockIdx.x;
    const int b = r >> 11;             // T = 2048
    const int tid = threadIdx.x;
    const float* __restrict__ row = inp + (size_t)r * Cc;
    const float4* __restrict__ row4 = (const float4*)row;

    float4 v[4];
    float m = NEGF;
    #pragma unroll
    for (int i = 0; i < 4; i++) {
        v[i] = row4[tid + 256 * i];
        m = fmaxf(m, fmaxf(fmaxf(v[i].x, v[i].y), fmaxf(v[i].z, v[i].w)));
    }

    __shared__ float s_red[32];
    #pragma unroll
    for (int off = 16; off; off >>= 1) m = fmaxf(m, __shfl_xor_sync(0xFFFFFFFFu, m, off));
    if ((tid & 31) == 0) s_red[tid >> 5] = m;
    __syncthreads();
    if (tid < 32) {
        float mm = (tid < 8) ? s_red[tid] : NEGF;
        #pragma unroll
        for (int off = 4; off; off >>= 1) mm = fmaxf(mm, __shfl_xor_sync(0xFFFFFFFFu, mm, off));
        if (tid == 0) s_red[0] = mm;
    }
    __syncthreads();
    m = s_red[0];

    float s = 0.f;
    #pragma unroll
    for (int i = 0; i < 4; i++) {
        s += __expf(v[i].x - m) + __expf(v[i].y - m) + __expf(v[i].z - m) + __expf(v[i].w - m);
    }
    #pragma unroll
    for (int off = 16; off; off >>= 1) s += __shfl_xor_sync(0xFFFFFFFFu, s, off);
    __shared__ float s_sum[8];
    if ((tid & 31) == 0) s_sum[tid >> 5] = s;
    __syncthreads();
    if (tid == 0) {
        float tot = 0.f;
        #pragma unroll
        for (int i = 0; i < 8; i++) tot += s_sum[i];
        s_red[0] = m + __logf(tot);   // lse (natural log domain)
    }
    __syncthreads();
    const float lse = s_red[0];

    if (tid < Uu) {
        const int base = b * Uu + tid;
        const int c = g_is64 ? t32[2 * base] : t32[base];
        g_lpt[(size_t)r * Uu + tid] = (row[c] - lse) * LOG2E;
    }
}

// ---------------------------------------------------------------------------
// Kernel 2: alpha recursion in log2 domain. One WARP per batch, no barriers.
// Lane j owns u = j*8 .. j*8+7 in registers; left-neighbor crosses lanes via
// one shfl_up per step. logaddexp2 tail = degree-4 polynomial (1 MUFU/elem).
// ---------------------------------------------------------------------------
__global__ __launch_bounds__(32) void alpha_kernel() {
    const int b = blockIdx.x;
    const int lane = threadIdx.x;
    const int lc = (lane < NLANE) ? lane : (NLANE - 1);    // clamp idle lanes
    const float* __restrict__ Lb = g_lpt + (size_t)b * Tt * Uu + lc * Kk;

    float a[Kk];
    #pragma unroll
    for (int k = 0; k < Kk; k++) a[k] = NEGF;
    if (lane == 0) a[0] = Lb[0];                           // lpt2[t=0][u=0]

    // depth-4 prefetch ring of lpt2[t][lc*8 .. lc*8+7]
    float4 pA[4], pB[4];
    #pragma unroll
    for (int i = 0; i < 4; i++) {
        const float4* p = (const float4*)(Lb + (size_t)(1 + i) * Uu);
        pA[i] = p[0]; pB[i] = p[1];
    }

    #pragma unroll 8
    for (int t = 1; t < Tt; t++) {
        const int slot = (t - 1) & 3;
        const float4 cA = pA[slot];
        const float4 cB = pB[slot];

        // prefetch t+4 (clamped; redundant tail loads are harmless)
        {
            int tp = t + 4; tp = (tp < Tt) ? tp : (Tt - 1);
            const float4* p = (const float4*)(Lb + (size_t)tp * Uu);
            pA[slot] = p[0]; pB[slot] = p[1];
        }

        float left_in = __shfl_up_sync(0xFFFFFFFFu, a[Kk - 1], 1);
        if (lane == 0) left_in = NEGF;

        float c[Kk] = {cA.x, cA.y, cA.z, cA.w, cB.x, cB.y, cB.z, cB.w};
        float lft[Kk];
        lft[0] = left_in;
        #pragma unroll
        for (int k = 1; k < Kk; k++) lft[k] = a[k - 1];

        // 8 independent logaddexp2's: mx + poly4(2^-|a-lft|)
        #pragma unroll
        for (int k = 0; k < Kk; k++) {
            const float mx = fmaxf(a[k], lft[k]);
            const float e  = ex2f(-fabsf(a[k] - lft[k]));   // MUFU with -|x| modifier
            float p = fmaf(Q4, e, Q3);
            p = fmaf(p, e, Q2);
            p = fmaf(p, e, Q1);
            p = fmaf(p, e, Q0);
            a[k] = (c[k] + mx) + p;
        }
    }

    if (lane == NLANE - 1) g_final[b] = a[Kk - 1];         // u = 199, log2 units
}

// ---------------------------------------------------------------------------
// Kernel 3: loss = mean_b(-alpha_final[b]) converted back to natural log.
// ---------------------------------------------------------------------------
__global__ void finish_kernel(float* __restrict__ out) {
    float s = 0.f;
    #pragma unroll
    for (int i = 0; i < Bb; i++) s += g_final[i];
    out[0] = -s * (LN2 / Bb);
}

extern "C" void kernel_launch(void* const* d_in, const int* in_sizes, int n_in,
                              void* d_out, int out_size) {
    int ii = 0, ti = 1;
    if (n_in >= 2 && in_sizes[0] < in_sizes[1]) { ii = 1; ti = 0; }
    const float* inp = (const float*)d_in[ii];
    const int*   t32 = (const int*)d_in[ti];
    float* out = (float*)d_out;

    detect_kernel<<<1, 1>>>(t32);
    lpt_kernel<<<Bb * Tt, 256>>>(inp, t32);
    alpha_kernel<<<Bb, 32>>>();
    finish_kernel<<<1, 1>>>(out);
}

// round 4
// speedup vs baseline: 1.3596x; 1.3596x over previous
#include <cuda_runtime.h>

#define Bb 8
#define Tt 2048
#define Cc 4096
#define Uu 200
#define NEGF (-1e30f)
#define LOG2E 1.4426950408889634f
#define LN2   0.6931471805599453f

#define NW   4      // warps per batch (one per SMSP)
#define UW   50     // u-range per warp
#define GG   8      // steps per wall-group (barrier cadence = skew quantum)
#define RING 32     // boundary ring depth (must cover 2-group reuse window)

// Scratch: lpt2 [B,T,U] fp32 (log2 domain) = 13.1 MB
__device__ float g_lpt[Bb * Tt * Uu];
__device__ float g_final[Bb];
__device__ int   g_pad;

__device__ __forceinline__ float ex2f(float x) {
    float r; asm("ex2.approx.f32 %0, %1;" : "=f"(r) : "f"(x)); return r;
}
__device__ __forceinline__ float lg2f(float x) {
    float r; asm("lg2.approx.f32 %0, %1;" : "=f"(r) : "f"(x)); return r;
}

// ---------------------------------------------------------------------------
// Kernel 1: per row r=b*T+t: lse = logsumexp(inputs[r,:]);
// g_lpt[r*U+u] = (inputs[r,targets[b,u]] - lse) * LOG2E.
// int64-vs-int32 targets detected inline (odd words of int64 are all zero).
// ---------------------------------------------------------------------------
__global__ __launch_bounds__(256) void lpt_kernel(const float* __restrict__ inp,
                                                  const int* __restrict__ t32) {
    const int r = blockIdx.x;
    const int b = r >> 11;             // T = 2048
    const int tid = threadIdx.x;
    const float* __restrict__ row = inp + (size_t)r * Cc;
    const float4* __restrict__ row4 = (const float4*)row;

    float4 v[4];
    float m = NEGF;
    #pragma unroll
    for (int i = 0; i < 4; i++) {
        v[i] = row4[tid + 256 * i];
        m = fmaxf(m, fmaxf(fmaxf(v[i].x, v[i].y), fmaxf(v[i].z, v[i].w)));
    }

    __shared__ float s_red[32];
    #pragma unroll
    for (int off = 16; off; off >>= 1) m = fmaxf(m, __shfl_xor_sync(0xFFFFFFFFu, m, off));
    if ((tid & 31) == 0) s_red[tid >> 5] = m;
    __syncthreads();
    if (tid < 32) {
        float mm = (tid < 8) ? s_red[tid] : NEGF;
        #pragma unroll
        for (int off = 4; off; off >>= 1) mm = fmaxf(mm, __shfl_xor_sync(0xFFFFFFFFu, mm, off));
        if (tid == 0) s_red[0] = mm;
    }
    __syncthreads();
    m = s_red[0];

    float s = 0.f;
    #pragma unroll
    for (int i = 0; i < 4; i++) {
        s += __expf(v[i].x - m) + __expf(v[i].y - m) + __expf(v[i].z - m) + __expf(v[i].w - m);
    }
    #pragma unroll
    for (int off = 16; off; off >>= 1) s += __shfl_xor_sync(0xFFFFFFFFu, s, off);
    __shared__ float s_sum[8];
    if ((tid & 31) == 0) s_sum[tid >> 5] = s;
    __syncthreads();
    if (tid == 0) {
        float tot = 0.f;
        #pragma unroll
        for (int i = 0; i < 8; i++) tot += s_sum[i];
        s_red[0] = m + __logf(tot);   // lse (natural log)
    }
    __syncthreads();
    const float lse = s_red[0];

    if (tid < Uu) {
        // int64 targets have zero odd 32-bit words (values < 4096)
        const int probe = t32[1] | t32[3] | t32[5] | t32[7] |
                          t32[9] | t32[11] | t32[13] | t32[15];
        const int base = b * Uu + tid;
        const int c = (probe == 0) ? t32[2 * base] : t32[base];
        g_lpt[(size_t)r * Uu + tid] = (row[c] - lse) * LOG2E;
    }
}

// ---------------------------------------------------------------------------
// Kernel 2: alpha recursion (log2 domain). One block of 4 warps per batch.
// Warp w owns u in [50w, 50w+50), lane j (0..24) owns u = 50w + 2j, +1.
// Warps run time-skewed by 8 steps: boundary alpha(u=50w+49) flows to warp
// w+1 through a smem ring; one __syncthreads per 8 steps publishes it.
// ---------------------------------------------------------------------------
__global__ __launch_bounds__(128) void alpha_kernel() {
    const int b    = blockIdx.x;
    const int w    = threadIdx.x >> 5;
    const int lane = threadIdx.x & 31;
    const int j    = (lane < 25) ? lane : 24;        // clamp idle lanes
    const int u0   = w * UW + 2 * j;
    const float* __restrict__ Lb = g_lpt + (size_t)b * Tt * Uu + u0;

    __shared__ float ring[NW][RING];
    for (int i = threadIdx.x; i < NW * RING; i += 128) ((float*)ring)[i] = NEGF;
    __syncthreads();

    float a0 = NEGF, a1 = NEGF;
    if (w == 0 && lane == 0) a0 = Lb[0];             // lpt2[t=0][u=0]

    // double-buffered per-group lpt tiles (float2 per lane per step)
    float2 bufA[GG], bufB[GG];
    #pragma unroll
    for (int s = 0; s < GG; s++)
        bufA[s] = *(const float2*)(Lb + (size_t)(1 + s) * Uu);

    // one recursion step at time t; CUR = this group's tile, NXT gets t+GG
    #define STEP(s, CUR, NXT)                                                   \
    {                                                                           \
        const int t = 8 * m + 1 + (s);                                          \
        if (t < Tt) {                                                           \
            int tp = t + GG; tp = (tp < Tt) ? tp : (Tt - 1);                    \
            NXT[s] = *(const float2*)(Lb + (size_t)tp * Uu);                    \
            float sh = __shfl_up_sync(0xFFFFFFFFu, a1, 1);                      \
            float lft0;                                                         \
            if (lane == 0)                                                      \
                lft0 = (w == 0) ? NEGF : ring[w - 1][(t - 1) & (RING - 1)];     \
            else lft0 = sh;                                                     \
            const float c0 = CUR[s].x, c1 = CUR[s].y;                           \
            const float mx0 = fmaxf(a0, lft0);                                  \
            const float e0  = ex2f(-fabsf(a0 - lft0));                          \
            const float p0  = lg2f(1.0f + e0);                                  \
            const float mx1 = fmaxf(a1, a0);                                    \
            const float e1  = ex2f(-fabsf(a1 - a0));                            \
            const float p1  = lg2f(1.0f + e1);                                  \
            a0 = (c0 + mx0) + p0;                                               \
            a1 = (c1 + mx1) + p1;                                               \
            if (lane == 24 && w < NW - 1) ring[w][t & (RING - 1)] = a1;         \
        }                                                                       \
    }

    #define GROUP(CUR, NXT)                                                     \
        STEP(0, CUR, NXT) STEP(1, CUR, NXT) STEP(2, CUR, NXT) STEP(3, CUR, NXT) \
        STEP(4, CUR, NXT) STEP(5, CUR, NXT) STEP(6, CUR, NXT) STEP(7, CUR, NXT)

    const int NGROUP_M = (Tt - 2) / GG + 1;          // 256 m-groups (t = 1..2047)
    for (int g = 0; g < NGROUP_M + NW - 1; g++) {
        const int m = g - w;
        if (m >= 0 && m < NGROUP_M) {
            if (!(m & 1)) { GROUP(bufA, bufB) }
            else         { GROUP(bufB, bufA) }
        }
        __syncthreads();                              // publish ring writes
    }

    if (w == NW - 1 && lane == 24) g_final[b] = a1;   // u = 199, t = 2047

    #undef STEP
    #undef GROUP
}

// ---------------------------------------------------------------------------
// Kernel 3: loss = mean_b(-alpha_final[b]) in natural-log units.
// ---------------------------------------------------------------------------
__global__ void finish_kernel(float* __restrict__ out) {
    float s = 0.f;
    #pragma unroll
    for (int i = 0; i < Bb; i++) s += g_final[i];
    out[0] = -s * (LN2 / Bb);
}

// Pad launch so ncu's "-s 5 -c 1" lands on alpha_kernel (6th launch overall).
__global__ void pad_kernel() { g_pad = 0; }

extern "C" void kernel_launch(void* const* d_in, const int* in_sizes, int n_in,
                              void* d_out, int out_size) {
    int ii = 0, ti = 1;
    if (n_in >= 2 && in_sizes[0] < in_sizes[1]) { ii = 1; ti = 0; }
    const float* inp = (const float*)d_in[ii];
    const int*   t32 = (const int*)d_in[ti];
    float* out = (float*)d_out;

    lpt_kernel<<<Bb * Tt, 256>>>(inp, t32);
    alpha_kernel<<<Bb, 128>>>();
    finish_kernel<<<1, 1>>>(out);
    pad_kernel<<<1, 1>>>();
}

// round 5
// speedup vs baseline: 1.4362x; 1.0564x over previous
#include <cuda_runtime.h>

#define Bb 8
#define Tt 2048
#define Cc 4096
#define Uu 200
#define NEGF (-1e30f)
#define LOG2E 1.4426950408889634f
#define LN2   0.6931471805599453f

#define NW   4      // warps per batch (one per SMSP)
#define UW   50     // u-range per warp
#define GG   8      // steps per group (barrier cadence = skew quantum)
#define RING 32     // boundary ring depth

// Scratch: lpt2 [B,T,U] fp32 (log2 domain) + 1 pad row for branch-free prefetch.
__device__ float g_lpt[Bb * Tt * Uu + Uu];
__device__ float g_final[Bb];
__device__ int   g_pad;

__device__ __forceinline__ float ex2f(float x) {
    float r; asm("ex2.approx.f32 %0, %1;" : "=f"(r) : "f"(x)); return r;
}
__device__ __forceinline__ float lg2f(float x) {
    float r; asm("lg2.approx.f32 %0, %1;" : "=f"(r) : "f"(x)); return r;
}

// ---------------------------------------------------------------------------
// Kernel 1: lse + gather, log2 domain. (Unchanged from R4 — ~55us, HBM-bound.)
// ---------------------------------------------------------------------------
__global__ __launch_bounds__(256) void lpt_kernel(const float* __restrict__ inp,
                                                  const int* __restrict__ t32) {
    const int r = blockIdx.x;
    const int b = r >> 11;             // T = 2048
    const int tid = threadIdx.x;
    const float* __restrict__ row = inp + (size_t)r * Cc;
    const float4* __restrict__ row4 = (const float4*)row;

    float4 v[4];
    float m = NEGF;
    #pragma unroll
    for (int i = 0; i < 4; i++) {
        v[i] = row4[tid + 256 * i];
        m = fmaxf(m, fmaxf(fmaxf(v[i].x, v[i].y), fmaxf(v[i].z, v[i].w)));
    }

    __shared__ float s_red[32];
    #pragma unroll
    for (int off = 16; off; off >>= 1) m = fmaxf(m, __shfl_xor_sync(0xFFFFFFFFu, m, off));
    if ((tid & 31) == 0) s_red[tid >> 5] = m;
    __syncthreads();
    if (tid < 32) {
        float mm = (tid < 8) ? s_red[tid] : NEGF;
        #pragma unroll
        for (int off = 4; off; off >>= 1) mm = fmaxf(mm, __shfl_xor_sync(0xFFFFFFFFu, mm, off));
        if (tid == 0) s_red[0] = mm;
    }
    __syncthreads();
    m = s_red[0];

    float s = 0.f;
    #pragma unroll
    for (int i = 0; i < 4; i++) {
        s += __expf(v[i].x - m) + __expf(v[i].y - m) + __expf(v[i].z - m) + __expf(v[i].w - m);
    }
    #pragma unroll
    for (int off = 16; off; off >>= 1) s += __shfl_xor_sync(0xFFFFFFFFu, s, off);
    __shared__ float s_sum[8];
    if ((tid & 31) == 0) s_sum[tid >> 5] = s;
    __syncthreads();
    if (tid == 0) {
        float tot = 0.f;
        #pragma unroll
        for (int i = 0; i < 8; i++) tot += s_sum[i];
        s_red[0] = m + __logf(tot);
    }
    __syncthreads();
    const float lse = s_red[0];

    if (tid < Uu) {
        // int64 targets have zero odd 32-bit words (values < 4096)
        const int probe = t32[1] | t32[3] | t32[5] | t32[7] |
                          t32[9] | t32[11] | t32[13] | t32[15];
        const int base = b * Uu + tid;
        const int c = (probe == 0) ? t32[2 * base] : t32[base];
        g_lpt[(size_t)r * Uu + tid] = (row[c] - lse) * LOG2E;
    }
}

// ---------------------------------------------------------------------------
// Branch-free group of NS recursion steps (t = 8m+1 .. 8m+NS).
// Ring traffic batched at group boundaries; no conditionals inside steps.
// ---------------------------------------------------------------------------
template<int NS, bool DOPF>
__device__ __forceinline__ void do_group(
    int m, int w, int lane,
    const float* __restrict__ Lb, float (*ring)[RING],
    float& a0, float& a1, float2 (&CUR)[GG], float2 (&NXT)[GG])
{
    const int R = (8 * m) & (RING - 1);               // aligned; R+7 <= 31, no wrap
    float rv[GG];
    if (lane == 0 && w > 0) {
        const float4 q0 = *(const float4*)&ring[w - 1][R];
        const float4 q1 = *(const float4*)&ring[w - 1][R + 4];
        rv[0] = q0.x; rv[1] = q0.y; rv[2] = q0.z; rv[3] = q0.w;
        rv[4] = q1.x; rv[5] = q1.y; rv[6] = q1.z; rv[7] = q1.w;
    } else {
        #pragma unroll
        for (int s = 0; s < GG; s++) rv[s] = NEGF;
    }

    const float* pf = Lb + (size_t)(8 * m + 1 + GG) * Uu;
    float hist[GG];

    #pragma unroll
    for (int s = 0; s < NS; s++) {
        if (DOPF) NXT[s] = *(const float2*)(pf + s * Uu);
        const float sh = __shfl_up_sync(0xFFFFFFFFu, a1, 1);
        const float lft0 = (lane == 0) ? rv[s] : sh;
        const float mx0 = fmaxf(a0, lft0);
        const float e0  = ex2f(-fabsf(a0 - lft0));
        const float p0  = lg2f(1.0f + e0);
        const float mx1 = fmaxf(a1, a0);
        const float e1  = ex2f(-fabsf(a1 - a0));
        const float p1  = lg2f(1.0f + e1);
        a0 = (CUR[s].x + mx0) + p0;
        a1 = (CUR[s].y + mx1) + p1;
        hist[s] = a1;
    }

    if (lane == 24 && w < NW - 1) {
        #pragma unroll
        for (int s = 0; s < NS; s++)
            ring[w][(R + 1 + s) & (RING - 1)] = hist[s];   // slot t&31 = a1(t)
    }
}

// ---------------------------------------------------------------------------
// Kernel 2: alpha recursion (log2 domain). 4 time-skewed warps per batch.
// Warp w owns u in [50w, 50w+50); lane j (0..24) owns u = 50w+2j, +1.
// ---------------------------------------------------------------------------
__global__ __launch_bounds__(128) void alpha_kernel() {
    const int b    = blockIdx.x;
    const int w    = threadIdx.x >> 5;
    const int lane = threadIdx.x & 31;
    const int j    = (lane < 25) ? lane : 24;        // clamp idle lanes
    const int u0   = w * UW + 2 * j;
    const float* __restrict__ Lb = g_lpt + (size_t)b * Tt * Uu + u0;

    __shared__ float ring[NW][RING];
    for (int i = threadIdx.x; i < NW * RING; i += 128) ((float*)ring)[i] = NEGF;
    __syncthreads();

    float a0 = NEGF, a1 = NEGF;
    if (w == 0 && lane == 0) a0 = Lb[0];             // lpt2[t=0][u=0]

    float2 bufA[GG], bufB[GG];
    #pragma unroll
    for (int s = 0; s < GG; s++)
        bufA[s] = *(const float2*)(Lb + (size_t)(1 + s) * Uu);

    const int NG = Tt / GG;                           // 256; groups m=0..255
    for (int g = 0; g < NG + NW - 1; g++) {
        const int m = g - w;
        if (m >= 0 && m < NG) {
            if (m == NG - 1) {                        // tail: t = 2041..2047
                if (m & 1) do_group<GG - 1, false>(m, w, lane, Lb, ring, a0, a1, bufB, bufA);
                else       do_group<GG - 1, false>(m, w, lane, Lb, ring, a0, a1, bufA, bufB);
            } else if (m & 1) {
                do_group<GG, true>(m, w, lane, Lb, ring, a0, a1, bufB, bufA);
            } else {
                do_group<GG, true>(m, w, lane, Lb, ring, a0, a1, bufA, bufB);
            }
        }
        __syncthreads();                              // publish ring writes
    }

    if (w == NW - 1 && lane == 24) g_final[b] = a1;   // u = 199, t = 2047
}

// ---------------------------------------------------------------------------
// Kernel 3: loss = mean_b(-alpha_final[b]) in natural-log units.
// ---------------------------------------------------------------------------
__global__ void finish_kernel(float* __restrict__ out) {
    float s = 0.f;
    #pragma unroll
    for (int i = 0; i < Bb; i++) s += g_final[i];
    out[0] = -s * (LN2 / Bb);
}

__global__ void pad_kernel()  { g_pad = 0; }
__global__ void pad_kernel2() { g_pad = 1; }

extern "C" void kernel_launch(void* const* d_in, const int* in_sizes, int n_in,
                              void* d_out, int out_size) {
    int ii = 0, ti = 1;
    if (n_in >= 2 && in_sizes[0] < in_sizes[1]) { ii = 1; ti = 0; }
    const float* inp = (const float*)d_in[ii];
    const int*   t32 = (const int*)d_in[ti];
    float* out = (float*)d_out;

    // ncu (-s 5 -c 1) lands on launch position 4 -> alpha_kernel.
    pad_kernel<<<1, 1>>>();
    lpt_kernel<<<Bb * Tt, 256>>>(inp, t32);
    pad_kernel2<<<1, 1>>>();
    alpha_kernel<<<Bb, 128>>>();
    finish_kernel<<<1, 1>>>(out);
}